// round 2
// baseline (speedup 1.0000x reference)
#include <cuda_runtime.h>
#include <math.h>

#define NN 4096
#define HH 64
#define G4 256
#define TT 48
#define MAXNZ 128
#define SZH (NN*HH)

// ---------------- device scratch (static, no allocation) ----------------
__device__ float g_dinv[NN];
__device__ int   g_cnt[NN];
__device__ int   g_cols[NN*MAXNZ];
__device__ float g_vals[NN*MAXNZ];
__device__ float g_Xall[NN*96];
__device__ float g_AX[NN*96];
__device__ float g_h0[2*SZH];
__device__ float g_h1[2*SZH];
__device__ float g_c0[SZH];
__device__ float g_c1[SZH];
__device__ float g_W0[128*G4];   // [gcWh0 ; liWh0]
__device__ float g_W1[256*G4];   // [gcWi1 ; liWi1 ; gcWh1 ; liWh1]
__device__ float g_b0[G4];
__device__ float g_b1[G4];
__device__ float g_WX[4*G4];     // [gcWi0 rows 0,1 ; liWi0 rows 0,1]

__device__ __forceinline__ float sigf(float x) { return 1.0f / (1.0f + expf(-x)); }

// ---------------- setup kernels ----------------

// d[r] = sum_c adj[r,c] + 1 (the +I);  dinv = d^-1/2
__global__ void deg_kernel(const float* __restrict__ adj) {
    __shared__ float red[256];
    const int r = blockIdx.x;
    float s = 0.0f;
    for (int c = threadIdx.x; c < NN; c += 256) s += adj[(long)r*NN + c];
    red[threadIdx.x] = s;
    __syncthreads();
    for (int o = 128; o > 0; o >>= 1) {
        if (threadIdx.x < o) red[threadIdx.x] += red[threadIdx.x + o];
        __syncthreads();
    }
    if (threadIdx.x == 0) g_dinv[r] = 1.0f / sqrtf(red[0] + 1.0f);
}

// Deterministic ELL build via ballot/popc compaction. val = (adj + I) * dinv_r * dinv_c.
__global__ void ell_kernel(const float* __restrict__ adj) {
    const int lane = threadIdx.x & 31;
    const int r = blockIdx.x * 8 + (threadIdx.x >> 5);
    const float dr = g_dinv[r];
    int base = 0;
    for (int c0 = 0; c0 < NN; c0 += 32) {
        const int c = c0 + lane;
        float a = adj[(long)r*NN + c];
        if (c == r) a += 1.0f;
        const unsigned m = __ballot_sync(0xffffffffu, a != 0.0f);
        if (a != 0.0f) {
            const int pos = base + __popc(m & ((1u << lane) - 1u));
            if (pos < MAXNZ) {
                g_cols[r*MAXNZ + pos] = c;
                g_vals[r*MAXNZ + pos] = a * dr * g_dinv[c];
            }
        }
        base += __popc(m);
    }
    if (lane == 0) g_cnt[r] = (base < MAXNZ) ? base : MAXNZ;
}

// x[1,T,N*2] -> Xall[n][2t+i]
__global__ void xall_kernel(const float* __restrict__ x) {
    const int idx = blockIdx.x * 256 + threadIdx.x;   // < NN*96
    const int n = idx / 96;
    const int q = idx - n * 96;
    const int t = q >> 1, i = q & 1;
    g_Xall[idx] = x[t * (NN*2) + n*2 + i];
}

// AX = A_norm @ Xall  (width 96), one warp per row
__global__ void spmm96_kernel() {
    const int lane = threadIdx.x & 31;
    const int r = blockIdx.x * 8 + (threadIdx.x >> 5);
    const int cn = g_cnt[r];
    const int*   cp = g_cols + r*MAXNZ;
    const float* vp = g_vals + r*MAXNZ;
    float a0 = 0.f, a1 = 0.f, a2 = 0.f;
    for (int k = 0; k < cn; k++) {
        const int c = cp[k]; const float v = vp[k];
        a0 += v * g_Xall[c*96 + lane];
        a1 += v * g_Xall[c*96 + lane + 32];
        a2 += v * g_Xall[c*96 + lane + 64];
    }
    g_AX[r*96 + lane]      = a0;
    g_AX[r*96 + lane + 32] = a1;
    g_AX[r*96 + lane + 64] = a2;
}

__global__ void setup_kernel(
    const float* __restrict__ gcWi0, const float* __restrict__ liWi0,
    const float* __restrict__ gcWh0, const float* __restrict__ liWh0,
    const float* __restrict__ gcWi1, const float* __restrict__ liWi1,
    const float* __restrict__ gcWh1, const float* __restrict__ liWh1,
    const float* __restrict__ gcbi0, const float* __restrict__ gcbh0,
    const float* __restrict__ libi0, const float* __restrict__ libh0,
    const float* __restrict__ gcbi1, const float* __restrict__ gcbh1,
    const float* __restrict__ libi1, const float* __restrict__ libh1)
{
    for (int idx = blockIdx.x*blockDim.x + threadIdx.x; idx < 65536;
         idx += gridDim.x*blockDim.x) {
        const int r = idx >> 8, c = idx & 255;
        const float* s1 = (r < 64) ? gcWi1 : (r < 128) ? liWi1 : (r < 192) ? gcWh1 : liWh1;
        g_W1[idx] = s1[(r & 63)*256 + c];
        if (r < 128) {
            const float* s0 = (r < 64) ? gcWh0 : liWh0;
            g_W0[idx] = s0[(r & 63)*256 + c];
        }
        if (r < 4)
            g_WX[idx] = (r < 2) ? gcWi0[r*256 + c] : liWi0[(r - 2)*256 + c];
        if (r == 0) {
            g_b0[c] = gcbi0[c] + gcbh0[c] + libi0[c] + libh0[c];
            g_b1[c] = gcbi1[c] + gcbh1[c] + libi1[c] + libh1[c];
        }
    }
}

__global__ void zero_kernel() {
    const int idx = blockIdx.x * 256 + threadIdx.x;  // < SZH
    g_h0[idx] = 0.f; g_h1[idx] = 0.f; g_c0[idx] = 0.f; g_c1[idx] = 0.f;
}

// ---------------- fused cell kernel ----------------
// Per 32-row tile: (1) SpMM-gather A@h into shared, stage h into shared,
// (2) register-blocked GEMM comb = [Ah|h(|Ah'|h')] @ Wcat (+ x rank-2 terms, layer 0),
// (3) LSTM gates -> new h, new c.  No intra-kernel cross-block dependency:
// comb row n needs only Ah row n, which gathers from the PREVIOUS kernel's h.
template<int LAYER>
__global__ void __launch_bounds__(256) cell_kernel(int pi, int t)
{
    constexpr int NSRC = (LAYER == 0) ? 1 : 2;
    constexpr int SRCF = NSRC * 4096;                 // floats in src region
    constexpr int BUFSZ = (SRCF + 4096 > 8192) ? (SRCF + 4096) : 8192;
    __shared__ float buf[BUFSZ];

    const int po = pi ^ 1;
    const float* __restrict__ hA   = (LAYER == 0) ? (g_h0 + pi*SZH) : (g_h0 + po*SZH);
    const float* __restrict__ hB   = g_h1 + pi*SZH;
    float*       __restrict__ hout = (LAYER == 0) ? (g_h0 + po*SZH) : (g_h1 + po*SZH);
    float*       __restrict__ cst  = (LAYER == 0) ? g_c0 : g_c1;
    const float* __restrict__ WCAT = (LAYER == 0) ? g_W0 : g_W1;
    const float* __restrict__ btot = (LAYER == 0) ? g_b0 : g_b1;

    const int tid = threadIdx.x;
    const int lane = tid & 31, warp = tid >> 5;
    const int r0 = blockIdx.x * 32;

    // stage h tiles (pair slots 1 and 3)
    for (int i = tid; i < 2048; i += 256) {
        buf[2048 + i] = hA[r0*64 + i];
        if (NSRC == 2) buf[6144 + i] = hB[r0*64 + i];
    }
    // SpMM: Ah tiles (pair slots 0 and 2); one warp per row, 4-way unrolled gather
    for (int rr = warp; rr < 32; rr += 8) {
        const int r = r0 + rr;
        const int cn = g_cnt[r];
        const int*   cp = g_cols + r*MAXNZ;
        const float* vp = g_vals + r*MAXNZ;
        float a00 = 0.f, a01 = 0.f, a10 = 0.f, a11 = 0.f;
        int k = 0;
        for (; k + 4 <= cn; k += 4) {
            const int   c0 = cp[k],   c1 = cp[k+1], c2 = cp[k+2], c3 = cp[k+3];
            const float v0 = vp[k],   v1 = vp[k+1], v2 = vp[k+2], v3 = vp[k+3];
            a00 += v0*hA[c0*64+lane]    + v1*hA[c1*64+lane]
                 + v2*hA[c2*64+lane]    + v3*hA[c3*64+lane];
            a01 += v0*hA[c0*64+lane+32] + v1*hA[c1*64+lane+32]
                 + v2*hA[c2*64+lane+32] + v3*hA[c3*64+lane+32];
            if (NSRC == 2) {
                a10 += v0*hB[c0*64+lane]    + v1*hB[c1*64+lane]
                     + v2*hB[c2*64+lane]    + v3*hB[c3*64+lane];
                a11 += v0*hB[c0*64+lane+32] + v1*hB[c1*64+lane+32]
                     + v2*hB[c2*64+lane+32] + v3*hB[c3*64+lane+32];
            }
        }
        for (; k < cn; k++) {
            const int c = cp[k]; const float v = vp[k];
            a00 += v*hA[c*64+lane]; a01 += v*hA[c*64+lane+32];
            if (NSRC == 2) { a10 += v*hB[c*64+lane]; a11 += v*hB[c*64+lane+32]; }
        }
        buf[rr*64 + lane] = a00; buf[rr*64 + lane + 32] = a01;
        if (NSRC == 2) {
            buf[4096 + rr*64 + lane] = a10; buf[4096 + rr*64 + lane + 32] = a11;
        }
    }

    // ---- GEMM: 32 rows x 256 cols per block; thread = 4 rows x (4+4 split cols) ----
    const int rb = tid >> 5;          // 0..7  -> rows rb*4..rb*4+3
    const int cb = tid & 31;
    const int ca  = cb * 4;           // cols [ca, ca+4)      (conflict-free LDS.128)
    const int cbx = 128 + cb * 4;     // cols [cbx, cbx+4)
    float acc[4][8];
    {
        const float4 b0 = *(const float4*)(btot + ca);
        const float4 b1 = *(const float4*)(btot + cbx);
        #pragma unroll
        for (int rr = 0; rr < 4; rr++) {
            acc[rr][0]=b0.x; acc[rr][1]=b0.y; acc[rr][2]=b0.z; acc[rr][3]=b0.w;
            acc[rr][4]=b1.x; acc[rr][5]=b1.y; acc[rr][6]=b1.z; acc[rr][7]=b1.w;
        }
    }
    float* Wsm = buf + SRCF;          // 16x256 W chunk
    #pragma unroll
    for (int p = 0; p < 2*NSRC; p++) {
        const float* srcp = buf + p * 2048;
        const float* Wp   = WCAT + p * 16384;     // pair = 64 K-rows
        #pragma unroll
        for (int kc = 0; kc < 4; kc++) {
            __syncthreads();                      // also closes phase 1 on first pass
            {
                float4* wd = (float4*)Wsm;
                const float4* ws = (const float4*)(Wp + kc * 4096);
                #pragma unroll
                for (int i = 0; i < 4; i++) wd[tid + i*256] = ws[tid + i*256];
            }
            __syncthreads();
            #pragma unroll
            for (int k4 = 0; k4 < 4; k4++) {
                float4 av[4];
                #pragma unroll
                for (int rr = 0; rr < 4; rr++)
                    av[rr] = *(const float4*)(srcp + (rb*4+rr)*64 + kc*16 + k4*4);
                #pragma unroll
                for (int kk = 0; kk < 4; kk++) {
                    const float4 w0 = *(const float4*)(Wsm + (k4*4+kk)*256 + ca);
                    const float4 w1 = *(const float4*)(Wsm + (k4*4+kk)*256 + cbx);
                    #pragma unroll
                    for (int rr = 0; rr < 4; rr++) {
                        const float a = (kk==0)?av[rr].x:(kk==1)?av[rr].y
                                       :(kk==2)?av[rr].z:av[rr].w;
                        acc[rr][0] += a*w0.x; acc[rr][1] += a*w0.y;
                        acc[rr][2] += a*w0.z; acc[rr][3] += a*w0.w;
                        acc[rr][4] += a*w1.x; acc[rr][5] += a*w1.y;
                        acc[rr][6] += a*w1.z; acc[rr][7] += a*w1.w;
                    }
                }
            }
        }
    }
    if (LAYER == 0) {   // rank-2 x terms: (A x_t)@gcWi0 + x_t@liWi0
        float4 wxa[4], wxb[4];
        #pragma unroll
        for (int j = 0; j < 4; j++) {
            wxa[j] = *(const float4*)(g_WX + j*256 + ca);
            wxb[j] = *(const float4*)(g_WX + j*256 + cbx);
        }
        #pragma unroll
        for (int rr = 0; rr < 4; rr++) {
            const int r = r0 + rb*4 + rr;
            const float s0 = g_AX  [r*96 + 2*t];
            const float s1 = g_AX  [r*96 + 2*t + 1];
            const float s2 = g_Xall[r*96 + 2*t];
            const float s3 = g_Xall[r*96 + 2*t + 1];
            acc[rr][0] += s0*wxa[0].x + s1*wxa[1].x + s2*wxa[2].x + s3*wxa[3].x;
            acc[rr][1] += s0*wxa[0].y + s1*wxa[1].y + s2*wxa[2].y + s3*wxa[3].y;
            acc[rr][2] += s0*wxa[0].z + s1*wxa[1].z + s2*wxa[2].z + s3*wxa[3].z;
            acc[rr][3] += s0*wxa[0].w + s1*wxa[1].w + s2*wxa[2].w + s3*wxa[3].w;
            acc[rr][4] += s0*wxb[0].x + s1*wxb[1].x + s2*wxb[2].x + s3*wxb[3].x;
            acc[rr][5] += s0*wxb[0].y + s1*wxb[1].y + s2*wxb[2].y + s3*wxb[3].y;
            acc[rr][6] += s0*wxb[0].z + s1*wxb[1].z + s2*wxb[2].z + s3*wxb[3].z;
            acc[rr][7] += s0*wxb[0].w + s1*wxb[1].w + s2*wxb[2].w + s3*wxb[3].w;
        }
    }

    // ---- gates: route comb through shared (overlays src region, post-sync) ----
    __syncthreads();
    #pragma unroll
    for (int rr = 0; rr < 4; rr++) {
        *(float4*)(buf + (rb*4+rr)*256 + ca)  =
            make_float4(acc[rr][0], acc[rr][1], acc[rr][2], acc[rr][3]);
        *(float4*)(buf + (rb*4+rr)*256 + cbx) =
            make_float4(acc[rr][4], acc[rr][5], acc[rr][6], acc[rr][7]);
    }
    __syncthreads();
    for (int i = tid; i < 2048; i += 256) {
        const int n = i >> 6, hc = i & 63;
        const float ig = buf[n*256 + hc];
        const float fg = buf[n*256 + 64  + hc];
        const float og = buf[n*256 + 128 + hc];
        const float gg = buf[n*256 + 192 + hc];
        const int g = (r0 + n)*64 + hc;
        const float cold = cst[g];
        const float cnew = sigf(fg)*cold + sigf(ig)*tanhf(gg);
        cst[g]  = cnew;
        hout[g] = sigf(og)*tanhf(cnew);
    }
}

// out[n,p] = h1_final[n,:] @ outW + outb
__global__ void outproj_kernel(const float* __restrict__ outW,
                               const float* __restrict__ outb,
                               float* __restrict__ out) {
    const int idx = blockIdx.x*blockDim.x + threadIdx.x;
    if (idx >= NN*12) return;
    const int n = idx / 12, p = idx - n*12;
    const float* h = g_h1 + n*64;    // final ping index 0 after t=47
    float s = outb[p];
    #pragma unroll
    for (int k = 0; k < 64; k++) s += h[k] * outW[k*12 + p];
    out[idx] = s;
}

// ---------------- launch ----------------
extern "C" void kernel_launch(void* const* d_in, const int* in_sizes, int n_in,
                              void* d_out, int out_size) {
    (void)in_sizes; (void)n_in; (void)out_size;
    const float* x     = (const float*)d_in[0];
    const float* adj   = (const float*)d_in[1];
    const float* gcWi0 = (const float*)d_in[2];
    const float* gcbi0 = (const float*)d_in[3];
    const float* gcWh0 = (const float*)d_in[4];
    const float* gcbh0 = (const float*)d_in[5];
    const float* liWi0 = (const float*)d_in[6];
    const float* libi0 = (const float*)d_in[7];
    const float* liWh0 = (const float*)d_in[8];
    const float* libh0 = (const float*)d_in[9];
    const float* gcWi1 = (const float*)d_in[10];
    const float* gcbi1 = (const float*)d_in[11];
    const float* gcWh1 = (const float*)d_in[12];
    const float* gcbh1 = (const float*)d_in[13];
    const float* liWi1 = (const float*)d_in[14];
    const float* libi1 = (const float*)d_in[15];
    const float* liWh1 = (const float*)d_in[16];
    const float* libh1 = (const float*)d_in[17];
    const float* outW  = (const float*)d_in[18];
    const float* outb  = (const float*)d_in[19];
    float* out = (float*)d_out;

    deg_kernel <<<NN, 256>>>(adj);
    ell_kernel <<<NN/8, 256>>>(adj);
    xall_kernel<<<(NN*96)/256, 256>>>(x);
    spmm96_kernel<<<NN/8, 256>>>();
    setup_kernel<<<64, 256>>>(gcWi0, liWi0, gcWh0, liWh0,
                              gcWi1, liWi1, gcWh1, liWh1,
                              gcbi0, gcbh0, libi0, libh0,
                              gcbi1, gcbh1, libi1, libh1);
    zero_kernel<<<SZH/256, 256>>>();

    for (int t = 0; t < TT; t++) {
        const int pi = t & 1;
        cell_kernel<0><<<NN/32, 256>>>(pi, t);
        cell_kernel<1><<<NN/32, 256>>>(pi, t);
    }
    outproj_kernel<<<(NN*12 + 255)/256, 256>>>(outW, outb, out);
}